// round 7
// baseline (speedup 1.0000x reference)
#include <cuda_runtime.h>
#include <cstdint>
#include <cmath>

// ---------------------------------------------------------------------------
// L1Wav prox: roll(S,S) -> 4-level periodized db4 DWT2 -> soft-threshold ->
// IDWT2 -> roll(-S,-S). Phase cancels exactly. SHIFT replicated on host.
//
// Two static float2 canvases (Mallat layout in A, ping-pong via B).
//   fwd0: input/A -> B    fwd1: B -> A (+ detail threshold)
//   inv1: A -> B          inv0: B -> A
// FINAL stage branches on out_size:
//   out_size >= 2*16M : d_out = float32 view of complex64 -> interleaved float2
//   else              : d_out = real-part-only float32 (64 MB) -> write e.x only
// ---------------------------------------------------------------------------

#define STR 4096u
#define NTOP 4096u
#define THRESH 0.005f

#define DECL_FILTERS \
    const float LO[8] = { \
        -0.010597401784997278f,  0.032883011666982945f,  0.030841381835986965f, \
        -0.18703481171888114f,  -0.02798376941698385f,   0.6308807679295904f, \
         0.7148465705525415f,    0.23037781330885523f }; \
    const float HI[8] = { \
         0.23037781330885523f,  -0.7148465705525415f,    0.6308807679295904f, \
         0.02798376941698385f,  -0.18703481171888114f,  -0.030841381835986965f, \
         0.032883011666982945f,  0.010597401784997278f };

__device__ float2 g_A[STR * STR];
__device__ float2 g_B[STR * STR];

__device__ __forceinline__ void fma2(float2& a, float c, float2 v) {
    a.x = fmaf(c, v.x, a.x);
    a.y = fmaf(c, v.y, a.y);
}

__device__ __forceinline__ float2 softt(float2 v) {
    float m2 = v.x * v.x + v.y * v.y;
    if (m2 <= THRESH * THRESH) return make_float2(0.f, 0.f);
    float s = 1.0f - THRESH * rsqrtf(m2);
    return make_float2(v.x * s, v.y * s);
}

// ---- forward axis0, level 0: fused input roll; (xr,xi) -> B ----
__global__ __launch_bounds__(256)
void k_fwd0_roll(const float* __restrict__ xr, const float* __restrict__ xi,
                 int sh) {
    DECL_FILTERS
    unsigned j = blockIdx.x * 256u + threadIdx.x;    // 0..4095
    unsigned n = blockIdx.y;                         // 0..2047
    unsigned jc = (j - (unsigned)sh + NTOP) & (NTOP - 1u);
    float2 a = {0.f, 0.f}, d = {0.f, 0.f};
#pragma unroll
    for (unsigned k = 0; k < 8; k++) {
        unsigned r = (2u * n + k - (unsigned)sh + NTOP) & (NTOP - 1u);
        float2 v = make_float2(xr[r * STR + jc], xi[r * STR + jc]);
        fma2(a, LO[k], v);
        fma2(d, HI[k], v);
    }
    g_B[n * STR + j] = a;
    g_B[(n + (NTOP >> 1)) * STR + j] = d;
}

// ---- forward axis0, generic level: A -> B ----
__global__ __launch_bounds__(256)
void k_fwd0(unsigned N) {
    DECL_FILTERS
    unsigned j = blockIdx.x * 256u + threadIdx.x;
    unsigned n = blockIdx.y;
    if (j >= N) return;
    unsigned h = N >> 1;
    float2 a = {0.f, 0.f}, d = {0.f, 0.f};
#pragma unroll
    for (unsigned k = 0; k < 8; k++) {
        unsigned r = (2u * n + k) & (N - 1u);
        float2 v = g_A[r * STR + j];
        fma2(a, LO[k], v);
        fma2(d, HI[k], v);
    }
    g_B[n * STR + j] = a;
    g_B[(n + h) * STR + j] = d;
}

// ---- forward axis1 + threshold details: B -> A ----
__global__ __launch_bounds__(256)
void k_fwd1(unsigned N) {
    DECL_FILTERS
    unsigned n = blockIdx.x * 256u + threadIdx.x;    // output col 0..h-1
    unsigned i = blockIdx.y;                         // row 0..N-1
    unsigned h = N >> 1;
    if (n >= h) return;
    float2 a = {0.f, 0.f}, d = {0.f, 0.f};
#pragma unroll
    for (unsigned k = 0; k < 8; k++) {
        unsigned c = (2u * n + k) & (N - 1u);
        float2 v = g_B[i * STR + c];
        fma2(a, LO[k], v);
        fma2(d, HI[k], v);
    }
    float2 left = (i < h) ? a : softt(a);    // LL untouched, HL thresholded
    g_A[i * STR + n] = left;
    g_A[i * STR + h + n] = softt(d);         // LH / HH thresholded
}

// ---- soft-threshold coarsest LL block (256x256) in place in A ----
__global__ __launch_bounds__(256)
void k_soft_ll() {
    unsigned idx = blockIdx.x * 256u + threadIdx.x;  // 0..65535
    unsigned i = idx >> 8, j = idx & 255u;
    g_A[i * STR + j] = softt(g_A[i * STR + j]);
}

// ---- inverse axis1: A quadrants -> stacked a/d in B ----
__global__ __launch_bounds__(256)
void k_inv1(unsigned N) {
    DECL_FILTERS
    unsigned p = blockIdx.x * 256u + threadIdx.x;    // 0..h-1
    unsigned i = blockIdx.y;                         // 0..N-1
    unsigned h = N >> 1;
    if (p >= h) return;
    float2 e = {0.f, 0.f}, o = {0.f, 0.f};
#pragma unroll
    for (unsigned q = 0; q < 4; q++) {
        unsigned pp = (p - q + h) & (h - 1u);
        float2 s = g_A[i * STR + pp];
        float2 t = g_A[i * STR + h + pp];
        fma2(e, LO[2 * q], s);     fma2(e, HI[2 * q], t);
        fma2(o, LO[2 * q + 1], s); fma2(o, HI[2 * q + 1], t);
    }
    g_B[i * STR + 2u * p]      = e;
    g_B[i * STR + 2u * p + 1u] = o;
}

// ---- inverse axis0: B stacked a/d -> A region ----
__global__ __launch_bounds__(256)
void k_inv0(unsigned N) {
    DECL_FILTERS
    unsigned j = blockIdx.x * 256u + threadIdx.x;
    unsigned p = blockIdx.y;                          // 0..h-1
    if (j >= N) return;
    unsigned h = N >> 1;
    float2 e = {0.f, 0.f}, o = {0.f, 0.f};
#pragma unroll
    for (unsigned q = 0; q < 4; q++) {
        unsigned pp = (p - q + h) & (h - 1u);
        float2 s = g_B[pp * STR + j];
        float2 t = g_B[(h + pp) * STR + j];
        fma2(e, LO[2 * q], s);     fma2(e, HI[2 * q], t);
        fma2(o, LO[2 * q + 1], s); fma2(o, HI[2 * q + 1], t);
    }
    g_A[(2u * p) * STR + j]      = e;
    g_A[(2u * p + 1u) * STR + j] = o;
}

// ---- final inverse axis0 + fused un-roll: B -> out (complex float2) ----
__global__ __launch_bounds__(256)
void k_inv0_out_c(float2* __restrict__ out, int sh) {
    DECL_FILTERS
    unsigned j = blockIdx.x * 256u + threadIdx.x;    // 0..4095
    unsigned p = blockIdx.y;                         // 0..2047
    unsigned h = NTOP >> 1;
    float2 e = {0.f, 0.f}, o = {0.f, 0.f};
#pragma unroll
    for (unsigned q = 0; q < 4; q++) {
        unsigned pp = (p - q + h) & (h - 1u);
        float2 s = g_B[pp * STR + j];
        float2 t = g_B[(h + pp) * STR + j];
        fma2(e, LO[2 * q], s);     fma2(e, HI[2 * q], t);
        fma2(o, LO[2 * q + 1], s); fma2(o, HI[2 * q + 1], t);
    }
    unsigned jc = (j - (unsigned)sh + NTOP) & (NTOP - 1u);
    unsigned r0 = (2u * p - (unsigned)sh + NTOP) & (NTOP - 1u);
    unsigned r1 = (2u * p + 1u - (unsigned)sh + NTOP) & (NTOP - 1u);
    out[r0 * NTOP + jc] = e;
    out[r1 * NTOP + jc] = o;
}

// ---- final inverse axis0 + fused un-roll: B -> out (REAL PART ONLY) ----
__global__ __launch_bounds__(256)
void k_inv0_out_r(float* __restrict__ out, int sh) {
    DECL_FILTERS
    unsigned j = blockIdx.x * 256u + threadIdx.x;    // 0..4095
    unsigned p = blockIdx.y;                         // 0..2047
    unsigned h = NTOP >> 1;
    float2 e = {0.f, 0.f}, o = {0.f, 0.f};
#pragma unroll
    for (unsigned q = 0; q < 4; q++) {
        unsigned pp = (p - q + h) & (h - 1u);
        float2 s = g_B[pp * STR + j];
        float2 t = g_B[(h + pp) * STR + j];
        fma2(e, LO[2 * q], s);     fma2(e, HI[2 * q], t);
        fma2(o, LO[2 * q + 1], s); fma2(o, HI[2 * q + 1], t);
    }
    unsigned jc = (j - (unsigned)sh + NTOP) & (NTOP - 1u);
    unsigned r0 = (2u * p - (unsigned)sh + NTOP) & (NTOP - 1u);
    unsigned r1 = (2u * p + 1u - (unsigned)sh + NTOP) & (NTOP - 1u);
    out[r0 * NTOP + jc] = e.x;
    out[r1 * NTOP + jc] = o.x;
}

// ---------------------------------------------------------------------------
// Host: replicate numpy default_rng(1000).uniform(-3,3) -> SHIFT
// ---------------------------------------------------------------------------
static int compute_shift() {
    const uint32_t MULT_A = 0x931e8875u, INIT_A = 0x43b0d7e5u;
    const uint32_t MULT_B = 0x58f38dedu, INIT_B = 0x8b51f9ddu;
    const uint32_t MIX_L = 0xca01f9ddu, MIX_R = 0x4973f715u;

    uint32_t hc = INIT_A;
    auto hashmix = [&](uint32_t v) -> uint32_t {
        v ^= hc; hc *= MULT_A; v *= hc; v ^= v >> 16; return v;
    };
    auto mix = [&](uint32_t x, uint32_t y) -> uint32_t {
        uint32_t r = (x * MIX_L) ^ (y * MIX_R); r ^= r >> 16; return r;
    };

    uint32_t pool[4];
    for (int i = 0; i < 4; i++) pool[i] = hashmix(i < 1 ? 1000u : 0u);
    for (int s = 0; s < 4; s++)
        for (int d = 0; d < 4; d++)
            if (s != d) pool[d] = mix(pool[d], hashmix(pool[s]));

    uint32_t st[8];
    uint32_t hb = INIT_B;
    for (int i = 0; i < 8; i++) {
        uint32_t v = pool[i & 3];
        v ^= hb; hb *= MULT_B; v *= hb; v ^= v >> 16;
        st[i] = v;
    }
    uint64_t w[4];
    for (int i = 0; i < 4; i++)
        w[i] = (uint64_t)st[2 * i] | ((uint64_t)st[2 * i + 1] << 32);

    typedef unsigned __int128 u128;
    const u128 MULT = ((u128)2549297995355413924ULL << 64) | 4865540595714422341ULL;
    u128 initstate = ((u128)w[0] << 64) | w[1];
    u128 initseq   = ((u128)w[2] << 64) | w[3];
    u128 state = 0;
    u128 inc = (initseq << 1) | 1;
    state = state * MULT + inc;
    state += initstate;
    state = state * MULT + inc;
    state = state * MULT + inc;      // first next_uint64
    uint64_t xo = (uint64_t)(state >> 64) ^ (uint64_t)state;
    unsigned rot = (unsigned)(state >> 122);
    uint64_t out64 = (xo >> rot) | (xo << ((64u - rot) & 63u));
    double dd = (double)(out64 >> 11) * (1.0 / 9007199254740992.0);
    double u = -3.0 + 6.0 * dd;
    return (int)nearbyint(u);
}

extern "C" void kernel_launch(void* const* d_in, const int* in_sizes, int n_in,
                              void* d_out, int out_size) {
    const float* xr = (const float*)d_in[0];
    const float* xi = (n_in >= 2) ? (const float*)d_in[1] : (const float*)d_in[0];
    const int sh = compute_shift();

    dim3 blk(256);

    // ---- forward (analysis), Mallat layout in A ----
    k_fwd0_roll<<<dim3(16, 2048), blk>>>(xr, xi, sh);
    k_fwd1<<<dim3(8, 4096), blk>>>(4096u);
    for (unsigned N = 2048; N >= 512; N >>= 1) {
        unsigned h = N >> 1;
        k_fwd0<<<dim3((N + 255) / 256, h), blk>>>(N);
        k_fwd1<<<dim3((h + 255) / 256, N), blk>>>(N);
    }

    // ---- threshold coarsest LL (256x256) ----
    k_soft_ll<<<dim3(256), blk>>>();

    // ---- inverse (synthesis) ----
    for (unsigned N = 512; N <= 2048; N <<= 1) {
        unsigned h = N >> 1;
        k_inv1<<<dim3((h + 255) / 256, N), blk>>>(N);
        k_inv0<<<dim3((N + 255) / 256, h), blk>>>(N);
    }
    k_inv1<<<dim3(8, 4096), blk>>>(4096u);

    // ---- final: branch on actual output capacity ----
    if (out_size >= 2 * 16777216) {
        // 33.5M+ float32 elements: interleaved complex view, 128 MB
        k_inv0_out_c<<<dim3(16, 2048), blk>>>((float2*)d_out, sh);
    } else {
        // 16.7M elements: assume real-only float32 (64 MB) -- crash-safe probe
        k_inv0_out_r<<<dim3(16, 2048), blk>>>((float*)d_out, sh);
    }
}